// round 8
// baseline (speedup 1.0000x reference)
#include <cuda_runtime.h>

// Problem constants
#define Bn 8
#define Nn 1024
#define Dn 512
#define Hn 8
#define DHn 64
#define BHn (Bn*Hn)          // 64
#define SCALE 0.125f         // 1/sqrt(64)

typedef unsigned long long ull;

__device__ __forceinline__ ull pk2(float lo, float hi) {
    ull r; asm("mov.b64 %0, {%1,%2};" : "=l"(r) : "f"(lo), "f"(hi)); return r;
}
__device__ __forceinline__ ull fma2(ull a, ull b, ull c) {
    ull d; asm("fma.rn.f32x2 %0, %1, %2, %3;" : "=l"(d) : "l"(a), "l"(b), "l"(c)); return d;
}
__device__ __forceinline__ ull add2(ull a, ull b) {
    ull d; asm("add.rn.f32x2 %0, %1, %2;" : "=l"(d) : "l"(a), "l"(b)); return d;
}
__device__ __forceinline__ float2 unpk(ull v) {
    float2 f; asm("mov.b64 {%0,%1}, %2;" : "=f"(f.x), "=f"(f.y) : "l"(v)); return f;
}

// Scratch (allocation-free rule: __device__ globals)
__device__ float g_q[(size_t)BHn*Nn*DHn];            // [bh, n, dh]
__device__ float g_k[(size_t)BHn*Nn*DHn];
__device__ float g_v[(size_t)BHn*Nn*DHn];
__device__ float g_otmp[(size_t)Bn*Nn*Dn];           // concat heads [b, n, h*dh]

// ---------------------------------------------------------------------------
// 128x128-tile NT GEMM, f32x2 packed: C[m,o] = sum_k A[m,k]*W[o,k]
// ---------------------------------------------------------------------------
template<int MODE>
__global__ __launch_bounds__(256) void gemm128(const float* __restrict__ A,
                                               const float* __restrict__ Wm,
                                               const float* __restrict__ bias,
                                               float* __restrict__ Cout)
{
    __shared__ float As[16][136];
    __shared__ float Bs[16][136];
    const int m0 = blockIdx.y * 128;
    const int n0 = blockIdx.x * 128;
    const int tid = threadIdx.x;
    const int tx = tid & 15, ty = tid >> 4;

    const float* Asrc = (MODE == 3) ? (const float*)g_otmp : A;

    ull acc[8][4];
#pragma unroll
    for (int i = 0; i < 8; i++)
#pragma unroll
        for (int p = 0; p < 4; p++) acc[i][p] = 0ULL;

    const int lrow = tid >> 1;          // 0..127
    const int lkk  = (tid & 1) * 8;     // 0,8

    for (int k0 = 0; k0 < Dn; k0 += 16) {
        float4 a0 = *(const float4*)(Asrc + (size_t)(m0 + lrow) * Dn + k0 + lkk);
        float4 a1 = *(const float4*)(Asrc + (size_t)(m0 + lrow) * Dn + k0 + lkk + 4);
        float4 b0 = *(const float4*)(Wm   + (size_t)(n0 + lrow) * Dn + k0 + lkk);
        float4 b1 = *(const float4*)(Wm   + (size_t)(n0 + lrow) * Dn + k0 + lkk + 4);
        As[lkk+0][lrow]=a0.x; As[lkk+1][lrow]=a0.y; As[lkk+2][lrow]=a0.z; As[lkk+3][lrow]=a0.w;
        As[lkk+4][lrow]=a1.x; As[lkk+5][lrow]=a1.y; As[lkk+6][lrow]=a1.z; As[lkk+7][lrow]=a1.w;
        Bs[lkk+0][lrow]=b0.x; Bs[lkk+1][lrow]=b0.y; Bs[lkk+2][lrow]=b0.z; Bs[lkk+3][lrow]=b0.w;
        Bs[lkk+4][lrow]=b1.x; Bs[lkk+5][lrow]=b1.y; Bs[lkk+6][lrow]=b1.z; Bs[lkk+7][lrow]=b1.w;
        __syncthreads();
#pragma unroll
        for (int k = 0; k < 16; k++) {
            float4 av0 = *(const float4*)&As[k][ty*4];
            float4 av1 = *(const float4*)&As[k][64 + ty*4];
            ulonglong2 b0v = *(const ulonglong2*)&Bs[k][tx*4];
            ulonglong2 b1v = *(const ulonglong2*)&Bs[k][64 + tx*4];
            ull pa[8], pb[4];
            pa[0]=pk2(av0.x,av0.x); pa[1]=pk2(av0.y,av0.y); pa[2]=pk2(av0.z,av0.z); pa[3]=pk2(av0.w,av0.w);
            pa[4]=pk2(av1.x,av1.x); pa[5]=pk2(av1.y,av1.y); pa[6]=pk2(av1.z,av1.z); pa[7]=pk2(av1.w,av1.w);
            pb[0]=b0v.x; pb[1]=b0v.y; pb[2]=b1v.x; pb[3]=b1v.y;
#pragma unroll
            for (int i = 0; i < 8; i++)
#pragma unroll
                for (int p = 0; p < 4; p++)
                    acc[i][p] = fma2(pa[i], pb[p], acc[i][p]);
        }
        __syncthreads();
    }

#pragma unroll
    for (int i = 0; i < 8; i++) {
        const int m = m0 + ((i < 4) ? (ty*4 + i) : (64 + ty*4 + i - 4));
#pragma unroll
        for (int p = 0; p < 4; p++) {
            const int o = n0 + ((p < 2) ? (tx*4 + p*2) : (64 + tx*4 + (p-2)*2));
            float2 v = unpk(acc[i][p]);
            if (MODE <= 2) {
                float* dst = (MODE == 0) ? g_q : (MODE == 1) ? g_k : g_v;
                const int bb = m >> 10, nn = m & (Nn - 1);
                const int hh = o >> 6,  dd = o & 63;
                *(float2*)&dst[(size_t)(((bb << 3) | hh) << 16) + (nn << 6) + dd] = v;
            } else {
                v.x += bias[o]; v.y += bias[o+1];
                *(float2*)&Cout[(size_t)m * Dn + o] = v;
            }
        }
    }
}

// ---------------------------------------------------------------------------
// Fused flash attention, tile 64i x 256j, 256 threads.
//  S micro: 8i x 8j.  S[i,j] = sum_d (SCALE*Q[d,i]) * (K[d,j] + E[d, j-i+off])
//  AV micro: 8i x 8d, 4-way k-split, merged once at end through smem.
// ---------------------------------------------------------------------------
#define JT 256
#define WIN 319
#define QS_ST 68
#define KS_ST 260
#define VS_ST 64
#define ES_ST 320
#define PS_ST 260
#define SM_KS_OFF (64*QS_ST)                 // 4352
#define SM_VS_OFF (SM_KS_OFF + 64*KS_ST)     // 20992
#define SM_EP_OFF (SM_VS_OFF + JT*VS_ST)     // 37376
#define SM_TOT    (SM_EP_OFF + 64*ES_ST)     // 57856 floats
#define SMEM_BYTES (SM_TOT * 4)              // 231424 B

__global__ __launch_bounds__(256, 1) void flash_attn(const float* __restrict__ Eg,
                                                     const float* __restrict__ phase)
{
    extern __shared__ float sm[];
    float* Qs = sm;                    // [64 d][QS_ST]: Qs[d*68 + i]   (pre-scaled)
    float* Ks = sm + SM_KS_OFF;        // [64 d][KS_ST]: Ks[d*260 + j]
    float* Vs = sm + SM_VS_OFF;        // [256 k][64 d]
    float* Es = sm + SM_EP_OFF;        // [64 d][ES_ST]: Es[d*320 + r]
    float* Ps = sm + SM_EP_OFF;        // union: [64 i][PS_ST]
    float* Om = sm + SM_EP_OFF;        // union: [4][64][64] merge buffer

    const int bh = blockIdx.y;
    const int i0 = blockIdx.x * 64;
    const int tid = threadIdx.x;
    const int tx = tid & 31;           // lane
    const int ty = tid >> 5;           // warp / i-group
    const int ib = ty * 8;
    const int jb = tx * 8;
    const int wb = jb - ib + 56;       // E window base, in [0,304], mult of 8
    const int lane = tx;
    const int grp  = ty;
    const int tk  = tx >> 3;           // AV k-quarter (0..3)
    const int dq  = (tx & 7) * 8;      // AV d-cols (8 wide)

    const float* qg = g_q + ((size_t)bh * Nn + i0) * DHn;
    const float* kg = g_k + (size_t)bh * Nn * DHn;
    const float* vg = g_v + (size_t)bh * Nn * DHn;

    // ---- load Q tile 64x64 -> d-major, pre-scaled by SCALE ----
#pragma unroll
    for (int u = 0; u < 4; u++) {
        const int r  = lane + (u & 1) * 32;
        const int c4 = grp * 4 + (u >> 1) * 32;
        float4 v = *(const float4*)(qg + r * DHn + c4);
        Qs[(c4+0)*QS_ST + r] = v.x * SCALE; Qs[(c4+1)*QS_ST + r] = v.y * SCALE;
        Qs[(c4+2)*QS_ST + r] = v.z * SCALE; Qs[(c4+3)*QS_ST + r] = v.w * SCALE;
    }

    ull o_acc[8][4];
    float m_i[8], l_i[8];
#pragma unroll
    for (int i = 0; i < 8; i++) {
        m_i[i] = -1e30f; l_i[i] = 0.f;
#pragma unroll
        for (int p = 0; p < 4; p++) o_acc[i][p] = 0ULL;
    }

    for (int j0 = 0; j0 < Nn; j0 += JT) {
        __syncthreads();   // prev tile AV done: Ks/Vs/Es(Ps) reusable

        // K tile 256x64 -> d-major
#pragma unroll
        for (int u = 0; u < 16; u++) {
            const int j  = lane + (u & 7) * 32;
            const int c4 = grp * 4 + (u >> 3) * 32;
            float4 v = *(const float4*)(kg + (size_t)(j0 + j) * DHn + c4);
            Ks[(c4+0)*KS_ST + j] = v.x; Ks[(c4+1)*KS_ST + j] = v.y;
            Ks[(c4+2)*KS_ST + j] = v.z; Ks[(c4+3)*KS_ST + j] = v.w;
        }
        // V tile 256x64 natural (coalesced)
#pragma unroll
        for (int u = 0; u < 16; u++) {
            const int idx = tid + u * 256;
            const int row = idx >> 4, c4 = (idx & 15) * 4;
            *(float4*)(Vs + row * VS_ST + c4) =
                *(const float4*)(vg + (size_t)(j0 + row) * DHn + c4);
        }
        // E window 319x64 -> d-major
        const int l0 = j0 - i0 + 960;
#pragma unroll
        for (int u = 0; u < 20; u++) {
            const int r  = lane + (u % 10) * 32;
            const int c4 = grp * 4 + (u / 10) * 32;
            if (r < WIN) {
                float4 v = *(const float4*)(Eg + (size_t)(l0 + r) * DHn + c4);
                Es[(c4+0)*ES_ST + r] = v.x; Es[(c4+1)*ES_ST + r] = v.y;
                Es[(c4+2)*ES_ST + r] = v.z; Es[(c4+3)*ES_ST + r] = v.w;
            }
        }
        __syncthreads();

        // ---- S = (SCALE*Q).(K+E), 8x8 micro ----
        ull sa[8][4];
#pragma unroll
        for (int i = 0; i < 8; i++)
#pragma unroll
            for (int p = 0; p < 4; p++) sa[i][p] = 0ULL;

#pragma unroll 4
        for (int d = 0; d < 64; d++) {
            float4 q0 = *(const float4*)(Qs + d * QS_ST + ib);
            float4 q1 = *(const float4*)(Qs + d * QS_ST + ib + 4);
            ulonglong2 kA = *(const ulonglong2*)(Ks + d * KS_ST + jb);
            ulonglong2 kB = *(const ulonglong2*)(Ks + d * KS_ST + jb + 4);
            float4 e0 = *(const float4*)(Es + d * ES_ST + wb);
            float4 e1 = *(const float4*)(Es + d * ES_ST + wb + 4);
            float4 e2 = *(const float4*)(Es + d * ES_ST + wb + 8);
            float4 e3 = *(const float4*)(Es + d * ES_ST + wb + 12);
            float e[16] = { e0.x,e0.y,e0.z,e0.w, e1.x,e1.y,e1.z,e1.w,
                            e2.x,e2.y,e2.z,e2.w, e3.x,e3.y,e3.z,e3.w };
            ull pa[8] = { pk2(q0.x,q0.x), pk2(q0.y,q0.y), pk2(q0.z,q0.z), pk2(q0.w,q0.w),
                          pk2(q1.x,q1.x), pk2(q1.y,q1.y), pk2(q1.z,q1.z), pk2(q1.w,q1.w) };
            ull pb[4] = { kA.x, kA.y, kB.x, kB.y };
            ull pr[14];
#pragma unroll
            for (int o = 0; o < 14; o++) pr[o] = pk2(e[o], e[o+1]);
#pragma unroll
            for (int i = 0; i < 8; i++)
#pragma unroll
                for (int p = 0; p < 4; p++) {
                    ull t = add2(pb[p], pr[2*p + 7 - i]);
                    sa[i][p] = fma2(pa[i], t, sa[i][p]);
                }
        }

        __syncthreads();   // ALL warps done reading Es before Ps overwrite

        // ---- fused online softmax + P write, per i (no s[8][8] storage) ----
#pragma unroll
        for (int i = 0; i < 8; i++) {
            float2 v0 = unpk(sa[i][0]);
            float2 v1 = unpk(sa[i][1]);
            float2 v2 = unpk(sa[i][2]);
            float2 v3 = unpk(sa[i][3]);
            float mx = fmaxf(fmaxf(fmaxf(v0.x, v0.y), fmaxf(v1.x, v1.y)),
                             fmaxf(fmaxf(v2.x, v2.y), fmaxf(v3.x, v3.y)));
#pragma unroll
            for (int o = 16; o; o >>= 1)
                mx = fmaxf(mx, __shfl_xor_sync(0xffffffffu, mx, o));
            const float mn = fmaxf(m_i[i], mx);
            const float al = __expf(m_i[i] - mn);
            m_i[i] = mn;
            float f0 = __expf(v0.x - mn), f1 = __expf(v0.y - mn);
            float f2 = __expf(v1.x - mn), f3 = __expf(v1.y - mn);
            float f4 = __expf(v2.x - mn), f5 = __expf(v2.y - mn);
            float f6 = __expf(v3.x - mn), f7 = __expf(v3.y - mn);
            float sum = ((f0 + f1) + (f2 + f3)) + ((f4 + f5) + (f6 + f7));
#pragma unroll
            for (int o = 16; o; o >>= 1)
                sum += __shfl_xor_sync(0xffffffffu, sum, o);
            l_i[i] = l_i[i] * al + sum;
            const ull aa = pk2(al, al);
#pragma unroll
            for (int p = 0; p < 4; p++)
                o_acc[i][p] = fma2(aa, o_acc[i][p], 0ULL);
            *(float4*)(Ps + (ib+i) * PS_ST + jb)     = make_float4(f0, f1, f2, f3);
            *(float4*)(Ps + (ib+i) * PS_ST + jb + 4) = make_float4(f4, f5, f6, f7);
        }
        __syncthreads();

        // ---- O += P @ V  (8i x 8d, k-quarter tk) ----
#pragma unroll 2
        for (int k4 = 0; k4 < 64; k4 += 4) {
            const int kk = tk * 64 + k4;
            float4 pv[8];
#pragma unroll
            for (int i = 0; i < 8; i++)
                pv[i] = *(const float4*)(Ps + (ib+i) * PS_ST + kk);
#pragma unroll
            for (int u = 0; u < 4; u++) {
                float4 va = *(const float4*)(Vs + (kk+u) * VS_ST + dq);
                float4 vb = *(const float4*)(Vs + (kk+u) * VS_ST + dq + 4);
                const ull* wa = (const ull*)&va;
                const ull* wbv = (const ull*)&vb;
#pragma unroll
                for (int i = 0; i < 8; i++) {
                    const float pf = (u == 0) ? pv[i].x : (u == 1) ? pv[i].y
                                   : (u == 2) ? pv[i].z : pv[i].w;
                    const ull pp = pk2(pf, pf);
                    o_acc[i][0] = fma2(pp, wa[0],  o_acc[i][0]);
                    o_acc[i][1] = fma2(pp, wa[1],  o_acc[i][1]);
                    o_acc[i][2] = fma2(pp, wbv[0], o_acc[i][2]);
                    o_acc[i][3] = fma2(pp, wbv[1], o_acc[i][3]);
                }
            }
        }
    }

    // ---- merge 4 k-quarters and epilogue ----
    __syncthreads();
#pragma unroll
    for (int i = 0; i < 8; i++)
#pragma unroll
        for (int p = 0; p < 4; p++) {
            float2 v = unpk(o_acc[i][p]);
            *(float2*)(Om + ((tk * 64 + ib + i) * 64 + dq + 2*p)) = v;
        }
    __syncthreads();

    if (tk == 0) {
        const int bb = bh >> 3, hh = bh & 7;
#pragma unroll
        for (int i = 0; i < 8; i++) {
            const int gi = i0 + ib + i;
            const float f = phase[(size_t)bh * Nn + gi] / l_i[i];
#pragma unroll
            for (int c = 0; c < 2; c++) {
                float4 a0 = *(const float4*)(Om + ((ib + i) * 64 + dq + c*4));
                float4 a1 = *(const float4*)(Om + ((64 + ib + i) * 64 + dq + c*4));
                float4 a2 = *(const float4*)(Om + ((128 + ib + i) * 64 + dq + c*4));
                float4 a3 = *(const float4*)(Om + ((192 + ib + i) * 64 + dq + c*4));
                float4 o;
                o.x = ((a0.x + a1.x) + (a2.x + a3.x)) * f;
                o.y = ((a0.y + a1.y) + (a2.y + a3.y)) * f;
                o.z = ((a0.z + a1.z) + (a2.z + a3.z)) * f;
                o.w = ((a0.w + a1.w) + (a2.w + a3.w)) * f;
                *(float4*)&g_otmp[(size_t)(bb * Nn + gi) * Dn + hh * 64 + dq + c*4] = o;
            }
        }
    }
}

// ---------------------------------------------------------------------------
extern "C" void kernel_launch(void* const* d_in, const int* in_sizes, int n_in,
                              void* d_out, int out_size)
{
    const float* x     = (const float*)d_in[0];
    const float* phase = (const float*)d_in[1];
    const float* E     = (const float*)d_in[2];
    const float* Wq    = (const float*)d_in[3];
    const float* Wk    = (const float*)d_in[4];
    const float* Wv    = (const float*)d_in[5];
    const float* Wo    = (const float*)d_in[6];
    const float* bo    = (const float*)d_in[7];
    float* out = (float*)d_out;

    static const bool s_init = []() {
        cudaFuncSetAttribute(flash_attn, cudaFuncAttributeMaxDynamicSharedMemorySize,
                             SMEM_BYTES);
        return true;
    }();
    (void)s_init;

    dim3 gproj(Dn / 128, (Bn * Nn) / 128);   // (4, 64)

    gemm128<0><<<gproj, 256>>>(x, Wq, nullptr, nullptr);
    gemm128<1><<<gproj, 256>>>(x, Wk, nullptr, nullptr);
    gemm128<2><<<gproj, 256>>>(x, Wv, nullptr, nullptr);

    flash_attn<<<dim3(Nn / 64, BHn), 256, SMEM_BYTES>>>(E, phase);

    gemm128<3><<<gproj, 256>>>(nullptr, Wo, bo, out);
}

// round 10
// speedup vs baseline: 1.0824x; 1.0824x over previous
#include <cuda_runtime.h>

// Problem constants
#define Bn 8
#define Nn 1024
#define Dn 512
#define Hn 8
#define DHn 64
#define BHn (Bn*Hn)          // 64
#define SCALE 0.125f         // 1/sqrt(64)

typedef unsigned long long ull;

__device__ __forceinline__ ull pk2(float lo, float hi) {
    ull r; asm("mov.b64 %0, {%1,%2};" : "=l"(r) : "f"(lo), "f"(hi)); return r;
}
__device__ __forceinline__ ull fma2(ull a, ull b, ull c) {
    ull d; asm("fma.rn.f32x2 %0, %1, %2, %3;" : "=l"(d) : "l"(a), "l"(b), "l"(c)); return d;
}
__device__ __forceinline__ ull add2(ull a, ull b) {
    ull d; asm("add.rn.f32x2 %0, %1, %2;" : "=l"(d) : "l"(a), "l"(b)); return d;
}
__device__ __forceinline__ float2 unpk(ull v) {
    float2 f; asm("mov.b64 {%0,%1}, %2;" : "=f"(f.x), "=f"(f.y) : "l"(v)); return f;
}

// Scratch (allocation-free rule: __device__ globals)
__device__ float g_q[(size_t)BHn*Nn*DHn];            // [bh, n, dh]
__device__ float g_k[(size_t)BHn*Nn*DHn];
__device__ float g_v[(size_t)BHn*Nn*DHn];
__device__ float g_otmp[(size_t)Bn*Nn*Dn];           // concat heads [b, n, h*dh]

// ---------------------------------------------------------------------------
// 128x128-tile NT GEMM, f32x2 packed: C[m,o] = sum_k A[m,k]*W[o,k]
// ---------------------------------------------------------------------------
template<int MODE>
__global__ __launch_bounds__(256) void gemm128(const float* __restrict__ A,
                                               const float* __restrict__ Wm,
                                               const float* __restrict__ bias,
                                               float* __restrict__ Cout)
{
    __shared__ float As[16][136];
    __shared__ float Bs[16][136];
    const int m0 = blockIdx.y * 128;
    const int n0 = blockIdx.x * 128;
    const int tid = threadIdx.x;
    const int tx = tid & 15, ty = tid >> 4;

    const float* Asrc = (MODE == 3) ? (const float*)g_otmp : A;

    ull acc[8][4];
#pragma unroll
    for (int i = 0; i < 8; i++)
#pragma unroll
        for (int p = 0; p < 4; p++) acc[i][p] = 0ULL;

    const int lrow = tid >> 1;          // 0..127
    const int lkk  = (tid & 1) * 8;     // 0,8

    for (int k0 = 0; k0 < Dn; k0 += 16) {
        float4 a0 = *(const float4*)(Asrc + (size_t)(m0 + lrow) * Dn + k0 + lkk);
        float4 a1 = *(const float4*)(Asrc + (size_t)(m0 + lrow) * Dn + k0 + lkk + 4);
        float4 b0 = *(const float4*)(Wm   + (size_t)(n0 + lrow) * Dn + k0 + lkk);
        float4 b1 = *(const float4*)(Wm   + (size_t)(n0 + lrow) * Dn + k0 + lkk + 4);
        As[lkk+0][lrow]=a0.x; As[lkk+1][lrow]=a0.y; As[lkk+2][lrow]=a0.z; As[lkk+3][lrow]=a0.w;
        As[lkk+4][lrow]=a1.x; As[lkk+5][lrow]=a1.y; As[lkk+6][lrow]=a1.z; As[lkk+7][lrow]=a1.w;
        Bs[lkk+0][lrow]=b0.x; Bs[lkk+1][lrow]=b0.y; Bs[lkk+2][lrow]=b0.z; Bs[lkk+3][lrow]=b0.w;
        Bs[lkk+4][lrow]=b1.x; Bs[lkk+5][lrow]=b1.y; Bs[lkk+6][lrow]=b1.z; Bs[lkk+7][lrow]=b1.w;
        __syncthreads();
#pragma unroll
        for (int k = 0; k < 16; k++) {
            float4 av0 = *(const float4*)&As[k][ty*4];
            float4 av1 = *(const float4*)&As[k][64 + ty*4];
            ulonglong2 b0v = *(const ulonglong2*)&Bs[k][tx*4];
            ulonglong2 b1v = *(const ulonglong2*)&Bs[k][64 + tx*4];
            ull pa[8], pb[4];
            pa[0]=pk2(av0.x,av0.x); pa[1]=pk2(av0.y,av0.y); pa[2]=pk2(av0.z,av0.z); pa[3]=pk2(av0.w,av0.w);
            pa[4]=pk2(av1.x,av1.x); pa[5]=pk2(av1.y,av1.y); pa[6]=pk2(av1.z,av1.z); pa[7]=pk2(av1.w,av1.w);
            pb[0]=b0v.x; pb[1]=b0v.y; pb[2]=b1v.x; pb[3]=b1v.y;
#pragma unroll
            for (int i = 0; i < 8; i++)
#pragma unroll
                for (int p = 0; p < 4; p++)
                    acc[i][p] = fma2(pa[i], pb[p], acc[i][p]);
        }
        __syncthreads();
    }

#pragma unroll
    for (int i = 0; i < 8; i++) {
        const int m = m0 + ((i < 4) ? (ty*4 + i) : (64 + ty*4 + i - 4));
#pragma unroll
        for (int p = 0; p < 4; p++) {
            const int o = n0 + ((p < 2) ? (tx*4 + p*2) : (64 + tx*4 + (p-2)*2));
            float2 v = unpk(acc[i][p]);
            if (MODE <= 2) {
                float* dst = (MODE == 0) ? g_q : (MODE == 1) ? g_k : g_v;
                const int bb = m >> 10, nn = m & (Nn - 1);
                const int hh = o >> 6,  dd = o & 63;
                *(float2*)&dst[(size_t)(((bb << 3) | hh) << 16) + (nn << 6) + dd] = v;
            } else {
                v.x += bias[o]; v.y += bias[o+1];
                *(float2*)&Cout[(size_t)m * Dn + o] = v;
            }
        }
    }
}

// ---------------------------------------------------------------------------
// Fused flash attention, tile 64i x 256j, 256 threads.
//  S micro: 8i x 8j.  S[i,j] = sum_d (SCALE*Q[d,i]) * (K[d,j] + E[d, j-i+off])
//  AV micro: 8i x 8d (cols c0..c0+3, c0+32..c0+35), 4-way k-split, merged once.
// ---------------------------------------------------------------------------
#define JT 256
#define WIN 319
#define QS_ST 68
#define KS_ST 260
#define VS_ST 64
#define ES_ST 320
#define PS_ST 260
#define SM_KS_OFF (64*QS_ST)                 // 4352
#define SM_VS_OFF (SM_KS_OFF + 64*KS_ST)     // 20992
#define SM_EP_OFF (SM_VS_OFF + JT*VS_ST)     // 37376
#define SM_TOT    (SM_EP_OFF + 64*ES_ST)     // 57856 floats
#define SMEM_BYTES (SM_TOT * 4)              // 231424 B

__global__ __launch_bounds__(256, 1) void flash_attn(const float* __restrict__ Eg,
                                                     const float* __restrict__ phase)
{
    extern __shared__ float sm[];
    float* Qs = sm;                    // [64 d][QS_ST]: Qs[d*68 + i]   (pre-scaled)
    float* Ks = sm + SM_KS_OFF;        // [64 d][KS_ST]: Ks[d*260 + j]
    float* Vs = sm + SM_VS_OFF;        // [256 k][64 d]
    float* Es = sm + SM_EP_OFF;        // [64 d][ES_ST]: Es[d*320 + r]
    float* Ps = sm + SM_EP_OFF;        // union: [64 i][PS_ST]
    float* Om = sm + SM_EP_OFF;        // union: [4][64][64] merge buffer

    const int bh = blockIdx.y;
    const int i0 = blockIdx.x * 64;
    const int tid = threadIdx.x;
    const int tx = tid & 31;           // lane
    const int ty = tid >> 5;           // warp / i-group
    const int ib = ty * 8;
    const int jb = tx * 8;
    const int wb = jb - ib + 56;       // E window base, in [0,304], mult of 8
    const int lane = tx;
    const int grp  = ty;
    const int tk  = tx >> 3;           // AV k-quarter (0..3)
    const int c0  = (tx & 7) * 4;      // AV d-col block A (B at c0+32)

    const float* qg = g_q + ((size_t)bh * Nn + i0) * DHn;
    const float* kg = g_k + (size_t)bh * Nn * DHn;
    const float* vg = g_v + (size_t)bh * Nn * DHn;

    // ---- load Q tile 64x64 -> d-major, pre-scaled by SCALE ----
#pragma unroll
    for (int u = 0; u < 4; u++) {
        const int r  = lane + (u & 1) * 32;
        const int c4 = grp * 4 + (u >> 1) * 32;
        float4 v = *(const float4*)(qg + r * DHn + c4);
        Qs[(c4+0)*QS_ST + r] = v.x * SCALE; Qs[(c4+1)*QS_ST + r] = v.y * SCALE;
        Qs[(c4+2)*QS_ST + r] = v.z * SCALE; Qs[(c4+3)*QS_ST + r] = v.w * SCALE;
    }

    ull o_acc[8][4];
    float m_i[8], l_i[8];
#pragma unroll
    for (int i = 0; i < 8; i++) {
        m_i[i] = -1e30f; l_i[i] = 0.f;
#pragma unroll
        for (int p = 0; p < 4; p++) o_acc[i][p] = 0ULL;
    }

    for (int j0 = 0; j0 < Nn; j0 += JT) {
        __syncthreads();   // prev tile AV done: Ks/Vs/Es(Ps) reusable

        // K tile 256x64 -> d-major
#pragma unroll
        for (int u = 0; u < 16; u++) {
            const int j  = lane + (u & 7) * 32;
            const int c4 = grp * 4 + (u >> 3) * 32;
            float4 v = *(const float4*)(kg + (size_t)(j0 + j) * DHn + c4);
            Ks[(c4+0)*KS_ST + j] = v.x; Ks[(c4+1)*KS_ST + j] = v.y;
            Ks[(c4+2)*KS_ST + j] = v.z; Ks[(c4+3)*KS_ST + j] = v.w;
        }
        // V tile 256x64 natural (coalesced)
#pragma unroll
        for (int u = 0; u < 16; u++) {
            const int idx = tid + u * 256;
            const int row = idx >> 4, c4 = (idx & 15) * 4;
            *(float4*)(Vs + row * VS_ST + c4) =
                *(const float4*)(vg + (size_t)(j0 + row) * DHn + c4);
        }
        // E window 319x64 -> d-major
        const int l0 = j0 - i0 + 960;
#pragma unroll
        for (int u = 0; u < 20; u++) {
            const int r  = lane + (u % 10) * 32;
            const int c4 = grp * 4 + (u / 10) * 32;
            if (r < WIN) {
                float4 v = *(const float4*)(Eg + (size_t)(l0 + r) * DHn + c4);
                Es[(c4+0)*ES_ST + r] = v.x; Es[(c4+1)*ES_ST + r] = v.y;
                Es[(c4+2)*ES_ST + r] = v.z; Es[(c4+3)*ES_ST + r] = v.w;
            }
        }
        __syncthreads();

        // ---- S = (SCALE*Q).(K+E), 8x8 micro ----
        ull sa[8][4];
#pragma unroll
        for (int i = 0; i < 8; i++)
#pragma unroll
            for (int p = 0; p < 4; p++) sa[i][p] = 0ULL;

#pragma unroll 4
        for (int d = 0; d < 64; d++) {
            float4 q0 = *(const float4*)(Qs + d * QS_ST + ib);
            float4 q1 = *(const float4*)(Qs + d * QS_ST + ib + 4);
            ulonglong2 kA = *(const ulonglong2*)(Ks + d * KS_ST + jb);
            ulonglong2 kB = *(const ulonglong2*)(Ks + d * KS_ST + jb + 4);
            float4 e0 = *(const float4*)(Es + d * ES_ST + wb);
            float4 e1 = *(const float4*)(Es + d * ES_ST + wb + 4);
            float4 e2 = *(const float4*)(Es + d * ES_ST + wb + 8);
            float4 e3 = *(const float4*)(Es + d * ES_ST + wb + 12);
            float e[16] = { e0.x,e0.y,e0.z,e0.w, e1.x,e1.y,e1.z,e1.w,
                            e2.x,e2.y,e2.z,e2.w, e3.x,e3.y,e3.z,e3.w };
            ull pa[8] = { pk2(q0.x,q0.x), pk2(q0.y,q0.y), pk2(q0.z,q0.z), pk2(q0.w,q0.w),
                          pk2(q1.x,q1.x), pk2(q1.y,q1.y), pk2(q1.z,q1.z), pk2(q1.w,q1.w) };
            ull pb[4] = { kA.x, kA.y, kB.x, kB.y };
            ull pr[14];
#pragma unroll
            for (int o = 0; o < 14; o++) pr[o] = pk2(e[o], e[o+1]);
#pragma unroll
            for (int i = 0; i < 8; i++)
#pragma unroll
                for (int p = 0; p < 4; p++) {
                    ull t = add2(pb[p], pr[2*p + 7 - i]);
                    sa[i][p] = fma2(pa[i], t, sa[i][p]);
                }
        }

        __syncthreads();   // ALL warps done reading Es before Ps overwrite

        // ---- fused online softmax + P write ----
#pragma unroll
        for (int i = 0; i < 8; i++) {
            float2 v0 = unpk(sa[i][0]);
            float2 v1 = unpk(sa[i][1]);
            float2 v2 = unpk(sa[i][2]);
            float2 v3 = unpk(sa[i][3]);
            float mx = fmaxf(fmaxf(fmaxf(v0.x, v0.y), fmaxf(v1.x, v1.y)),
                             fmaxf(fmaxf(v2.x, v2.y), fmaxf(v3.x, v3.y)));
#pragma unroll
            for (int o = 16; o; o >>= 1)
                mx = fmaxf(mx, __shfl_xor_sync(0xffffffffu, mx, o));
            const float mn = fmaxf(m_i[i], mx);
            const float al = __expf(m_i[i] - mn);
            m_i[i] = mn;
            float f0 = __expf(v0.x - mn), f1 = __expf(v0.y - mn);
            float f2 = __expf(v1.x - mn), f3 = __expf(v1.y - mn);
            float f4 = __expf(v2.x - mn), f5 = __expf(v2.y - mn);
            float f6 = __expf(v3.x - mn), f7 = __expf(v3.y - mn);
            float sum = ((f0 + f1) + (f2 + f3)) + ((f4 + f5) + (f6 + f7));
#pragma unroll
            for (int o = 16; o; o >>= 1)
                sum += __shfl_xor_sync(0xffffffffu, sum, o);
            l_i[i] = l_i[i] * al + sum;
            const ull aa = pk2(al, al);
#pragma unroll
            for (int p = 0; p < 4; p++)
                o_acc[i][p] = fma2(aa, o_acc[i][p], 0ULL);
            *(float4*)(Ps + (ib+i) * PS_ST + jb)     = make_float4(f0, f1, f2, f3);
            *(float4*)(Ps + (ib+i) * PS_ST + jb + 4) = make_float4(f4, f5, f6, f7);
        }
        __syncthreads();

        // ---- O += P @ V  (8i x 8d: cols c0..c0+3 and c0+32..c0+35, k-quarter tk) ----
#pragma unroll 2
        for (int k4 = 0; k4 < 64; k4 += 4) {
            const int kk = tk * 64 + k4;
            float4 pv[8];
#pragma unroll
            for (int i = 0; i < 8; i++)
                pv[i] = *(const float4*)(Ps + (ib+i) * PS_ST + kk);
#pragma unroll
            for (int u = 0; u < 4; u++) {
                float4 va = *(const float4*)(Vs + (kk+u) * VS_ST + c0);        // 16B lane stride: conflict-free
                float4 vb = *(const float4*)(Vs + (kk+u) * VS_ST + c0 + 32);
                const ull* wa = (const ull*)&va;
                const ull* wv = (const ull*)&vb;
#pragma unroll
                for (int i = 0; i < 8; i++) {
                    const float pf = (u == 0) ? pv[i].x : (u == 1) ? pv[i].y
                                   : (u == 2) ? pv[i].z : pv[i].w;
                    const ull pp = pk2(pf, pf);
                    o_acc[i][0] = fma2(pp, wa[0], o_acc[i][0]);
                    o_acc[i][1] = fma2(pp, wa[1], o_acc[i][1]);
                    o_acc[i][2] = fma2(pp, wv[0], o_acc[i][2]);
                    o_acc[i][3] = fma2(pp, wv[1], o_acc[i][3]);
                }
            }
        }
    }

    // ---- merge 4 k-quarters and epilogue ----
    __syncthreads();
#pragma unroll
    for (int i = 0; i < 8; i++)
#pragma unroll
        for (int p = 0; p < 4; p++) {
            float2 v = unpk(o_acc[i][p]);
            const int col = (p < 2) ? (c0 + 2*p) : (c0 + 32 + 2*(p-2));
            *(float2*)(Om + ((tk * 64 + ib + i) * 64 + col)) = v;
        }
    __syncthreads();

    if (tk == 0) {
        const int bb = bh >> 3, hh = bh & 7;
#pragma unroll
        for (int i = 0; i < 8; i++) {
            const int gi = i0 + ib + i;
            const float f = phase[(size_t)bh * Nn + gi] / l_i[i];
#pragma unroll
            for (int half = 0; half < 2; half++) {
                const int c = c0 + half * 32;
                float4 a0 = *(const float4*)(Om + ((ib + i) * 64 + c));
                float4 a1 = *(const float4*)(Om + ((64 + ib + i) * 64 + c));
                float4 a2 = *(const float4*)(Om + ((128 + ib + i) * 64 + c));
                float4 a3 = *(const float4*)(Om + ((192 + ib + i) * 64 + c));
                float4 o;
                o.x = ((a0.x + a1.x) + (a2.x + a3.x)) * f;
                o.y = ((a0.y + a1.y) + (a2.y + a3.y)) * f;
                o.z = ((a0.z + a1.z) + (a2.z + a3.z)) * f;
                o.w = ((a0.w + a1.w) + (a2.w + a3.w)) * f;
                *(float4*)&g_otmp[(size_t)(bb * Nn + gi) * Dn + hh * 64 + c] = o;
            }
        }
    }
}

// ---------------------------------------------------------------------------
extern "C" void kernel_launch(void* const* d_in, const int* in_sizes, int n_in,
                              void* d_out, int out_size)
{
    const float* x     = (const float*)d_in[0];
    const float* phase = (const float*)d_in[1];
    const float* E     = (const float*)d_in[2];
    const float* Wq    = (const float*)d_in[3];
    const float* Wk    = (const float*)d_in[4];
    const float* Wv    = (const float*)d_in[5];
    const float* Wo    = (const float*)d_in[6];
    const float* bo    = (const float*)d_in[7];
    float* out = (float*)d_out;

    static const bool s_init = []() {
        cudaFuncSetAttribute(flash_attn, cudaFuncAttributeMaxDynamicSharedMemorySize,
                             SMEM_BYTES);
        return true;
    }();
    (void)s_init;

    dim3 gproj(Dn / 128, (Bn * Nn) / 128);   // (4, 64)

    gemm128<0><<<gproj, 256>>>(x, Wq, nullptr, nullptr);
    gemm128<1><<<gproj, 256>>>(x, Wk, nullptr, nullptr);
    gemm128<2><<<gproj, 256>>>(x, Wv, nullptr, nullptr);

    flash_attn<<<dim3(Nn / 64, BHn), 256, SMEM_BYTES>>>(E, phase);

    gemm128<3><<<gproj, 256>>>(nullptr, Wo, bo, out);
}

// round 11
// speedup vs baseline: 1.1097x; 1.0252x over previous
#include <cuda_runtime.h>

// Problem constants
#define Bn 8
#define Nn 1024
#define Dn 512
#define Hn 8
#define DHn 64
#define BHn (Bn*Hn)          // 64
#define SCALE 0.125f         // 1/sqrt(64)

typedef unsigned long long ull;

__device__ __forceinline__ ull pk2(float lo, float hi) {
    ull r; asm("mov.b64 %0, {%1,%2};" : "=l"(r) : "f"(lo), "f"(hi)); return r;
}
__device__ __forceinline__ ull fma2(ull a, ull b, ull c) {
    ull d; asm("fma.rn.f32x2 %0, %1, %2, %3;" : "=l"(d) : "l"(a), "l"(b), "l"(c)); return d;
}
__device__ __forceinline__ ull add2(ull a, ull b) {
    ull d; asm("add.rn.f32x2 %0, %1, %2;" : "=l"(d) : "l"(a), "l"(b)); return d;
}
__device__ __forceinline__ float2 unpk(ull v) {
    float2 f; asm("mov.b64 {%0,%1}, %2;" : "=f"(f.x), "=f"(f.y) : "l"(v)); return f;
}

// Scratch (allocation-free rule: __device__ globals)
__device__ float g_q[(size_t)BHn*Nn*DHn];            // [bh, n, dh]
__device__ float g_k[(size_t)BHn*Nn*DHn];
__device__ float g_v[(size_t)BHn*Nn*DHn];
__device__ float g_otmp[(size_t)Bn*Nn*Dn];           // concat heads [b, n, h*dh]

// ---------------------------------------------------------------------------
// 128x128-tile NT GEMM, f32x2 packed: C[m,o] = sum_k A[m,k]*W[o,k]
// ---------------------------------------------------------------------------
template<int MODE>
__global__ __launch_bounds__(256) void gemm128(const float* __restrict__ A,
                                               const float* __restrict__ Wm,
                                               const float* __restrict__ bias,
                                               float* __restrict__ Cout)
{
    __shared__ float As[16][136];
    __shared__ float Bs[16][136];
    const int m0 = blockIdx.y * 128;
    const int n0 = blockIdx.x * 128;
    const int tid = threadIdx.x;
    const int tx = tid & 15, ty = tid >> 4;

    const float* Asrc = (MODE == 3) ? (const float*)g_otmp : A;

    ull acc[8][4];
#pragma unroll
    for (int i = 0; i < 8; i++)
#pragma unroll
        for (int p = 0; p < 4; p++) acc[i][p] = 0ULL;

    const int lrow = tid >> 1;          // 0..127
    const int lkk  = (tid & 1) * 8;     // 0,8

    for (int k0 = 0; k0 < Dn; k0 += 16) {
        float4 a0 = *(const float4*)(Asrc + (size_t)(m0 + lrow) * Dn + k0 + lkk);
        float4 a1 = *(const float4*)(Asrc + (size_t)(m0 + lrow) * Dn + k0 + lkk + 4);
        float4 b0 = *(const float4*)(Wm   + (size_t)(n0 + lrow) * Dn + k0 + lkk);
        float4 b1 = *(const float4*)(Wm   + (size_t)(n0 + lrow) * Dn + k0 + lkk + 4);
        As[lkk+0][lrow]=a0.x; As[lkk+1][lrow]=a0.y; As[lkk+2][lrow]=a0.z; As[lkk+3][lrow]=a0.w;
        As[lkk+4][lrow]=a1.x; As[lkk+5][lrow]=a1.y; As[lkk+6][lrow]=a1.z; As[lkk+7][lrow]=a1.w;
        Bs[lkk+0][lrow]=b0.x; Bs[lkk+1][lrow]=b0.y; Bs[lkk+2][lrow]=b0.z; Bs[lkk+3][lrow]=b0.w;
        Bs[lkk+4][lrow]=b1.x; Bs[lkk+5][lrow]=b1.y; Bs[lkk+6][lrow]=b1.z; Bs[lkk+7][lrow]=b1.w;
        __syncthreads();
#pragma unroll
        for (int k = 0; k < 16; k++) {
            float4 av0 = *(const float4*)&As[k][ty*4];
            float4 av1 = *(const float4*)&As[k][64 + ty*4];
            ulonglong2 b0v = *(const ulonglong2*)&Bs[k][tx*4];
            ulonglong2 b1v = *(const ulonglong2*)&Bs[k][64 + tx*4];
            ull pa[8], pb[4];
            pa[0]=pk2(av0.x,av0.x); pa[1]=pk2(av0.y,av0.y); pa[2]=pk2(av0.z,av0.z); pa[3]=pk2(av0.w,av0.w);
            pa[4]=pk2(av1.x,av1.x); pa[5]=pk2(av1.y,av1.y); pa[6]=pk2(av1.z,av1.z); pa[7]=pk2(av1.w,av1.w);
            pb[0]=b0v.x; pb[1]=b0v.y; pb[2]=b1v.x; pb[3]=b1v.y;
#pragma unroll
            for (int i = 0; i < 8; i++)
#pragma unroll
                for (int p = 0; p < 4; p++)
                    acc[i][p] = fma2(pa[i], pb[p], acc[i][p]);
        }
        __syncthreads();
    }

#pragma unroll
    for (int i = 0; i < 8; i++) {
        const int m = m0 + ((i < 4) ? (ty*4 + i) : (64 + ty*4 + i - 4));
#pragma unroll
        for (int p = 0; p < 4; p++) {
            const int o = n0 + ((p < 2) ? (tx*4 + p*2) : (64 + tx*4 + (p-2)*2));
            float2 v = unpk(acc[i][p]);
            if (MODE <= 2) {
                float* dst = (MODE == 0) ? g_q : (MODE == 1) ? g_k : g_v;
                const int bb = m >> 10, nn = m & (Nn - 1);
                const int hh = o >> 6,  dd = o & 63;
                *(float2*)&dst[(size_t)(((bb << 3) | hh) << 16) + (nn << 6) + dd] = v;
            } else {
                v.x += bias[o]; v.y += bias[o+1];
                *(float2*)&Cout[(size_t)m * Dn + o] = v;
            }
        }
    }
}

// ---------------------------------------------------------------------------
// Fused flash attention, tile 64i x 256j, 256 threads.
//  S micro: 8i x 8j.  S[i,j] = sum_d (SCALE*Q[d,i]) * (K[d,j] + E[d, j-i+off])
//  AV micro: 8i x 8d (cols c0..c0+3, c0+32..c0+35), 4-way k-split.
//  Pipelining: Ps lives in the Ks region (dead after S); next tile's E window
//  is prefetched into the Es region overlapped with the AV compute phase.
// ---------------------------------------------------------------------------
#define JT 256
#define WIN 319
#define QS_ST 68
#define KS_ST 260
#define VS_ST 64
#define ES_ST 320
#define PS_ST 260
#define SM_KS_OFF (64*QS_ST)                 // 4352
#define SM_VS_OFF (SM_KS_OFF + 64*KS_ST)     // 20992
#define SM_EP_OFF (SM_VS_OFF + JT*VS_ST)     // 37376
#define SM_TOT    (SM_EP_OFF + 64*ES_ST)     // 57856 floats
#define SMEM_BYTES (SM_TOT * 4)              // 231424 B

__global__ __launch_bounds__(256, 1) void flash_attn(const float* __restrict__ Eg,
                                                     const float* __restrict__ phase)
{
    extern __shared__ float sm[];
    float* Qs = sm;                    // [64 d][QS_ST]: Qs[d*68 + i]   (pre-scaled)
    float* Ks = sm + SM_KS_OFF;        // [64 d][KS_ST]: Ks[d*260 + j]
    float* Vs = sm + SM_VS_OFF;        // [256 k][64 d]
    float* Es = sm + SM_EP_OFF;        // [64 d][ES_ST]: Es[d*320 + r]
    float* Ps = sm + SM_KS_OFF;        // union with Ks: [64 i][PS_ST]
    float* Om = sm + SM_EP_OFF;        // union with Es: [4][64][64] merge buffer

    const int bh = blockIdx.y;
    const int i0 = blockIdx.x * 64;
    const int tid = threadIdx.x;
    const int tx = tid & 31;           // lane
    const int ty = tid >> 5;           // warp / i-group
    const int ib = ty * 8;
    const int jb = tx * 8;
    const int wb = jb - ib + 56;       // E window base, in [0,304], mult of 8
    const int lane = tx;
    const int grp  = ty;
    const int tk  = tx >> 3;           // AV k-quarter (0..3)
    const int c0  = (tx & 7) * 4;      // AV d-col block A (B at c0+32)

    const float* qg = g_q + ((size_t)bh * Nn + i0) * DHn;
    const float* kg = g_k + (size_t)bh * Nn * DHn;
    const float* vg = g_v + (size_t)bh * Nn * DHn;

    // ---- load Q tile 64x64 -> d-major, pre-scaled by SCALE ----
#pragma unroll
    for (int u = 0; u < 4; u++) {
        const int r  = lane + (u & 1) * 32;
        const int c4 = grp * 4 + (u >> 1) * 32;
        float4 v = *(const float4*)(qg + r * DHn + c4);
        Qs[(c4+0)*QS_ST + r] = v.x * SCALE; Qs[(c4+1)*QS_ST + r] = v.y * SCALE;
        Qs[(c4+2)*QS_ST + r] = v.z * SCALE; Qs[(c4+3)*QS_ST + r] = v.w * SCALE;
    }

    // ---- prologue: E window for tile 0 ----
    {
        const int l0 = 0 - i0 + 960;
#pragma unroll
        for (int u = 0; u < 20; u++) {
            const int r  = lane + (u % 10) * 32;
            const int c4 = grp * 4 + (u / 10) * 32;
            if (r < WIN) {
                float4 v = *(const float4*)(Eg + (size_t)(l0 + r) * DHn + c4);
                Es[(c4+0)*ES_ST + r] = v.x; Es[(c4+1)*ES_ST + r] = v.y;
                Es[(c4+2)*ES_ST + r] = v.z; Es[(c4+3)*ES_ST + r] = v.w;
            }
        }
    }

    ull o_acc[8][4];
    float m_i[8], l_i[8];
#pragma unroll
    for (int i = 0; i < 8; i++) {
        m_i[i] = -1e30f; l_i[i] = 0.f;
#pragma unroll
        for (int p = 0; p < 4; p++) o_acc[i][p] = 0ULL;
    }

    for (int j0 = 0; j0 < Nn; j0 += JT) {
        __syncthreads();   // prev AV done (Ps in Ks region free; Vs free)

        // K tile 256x64 -> d-major
#pragma unroll
        for (int u = 0; u < 16; u++) {
            const int j  = lane + (u & 7) * 32;
            const int c4 = grp * 4 + (u >> 3) * 32;
            float4 v = *(const float4*)(kg + (size_t)(j0 + j) * DHn + c4);
            Ks[(c4+0)*KS_ST + j] = v.x; Ks[(c4+1)*KS_ST + j] = v.y;
            Ks[(c4+2)*KS_ST + j] = v.z; Ks[(c4+3)*KS_ST + j] = v.w;
        }
        // V tile 256x64 natural (coalesced)
#pragma unroll
        for (int u = 0; u < 16; u++) {
            const int idx = tid + u * 256;
            const int row = idx >> 4, c4 = (idx & 15) * 4;
            *(float4*)(Vs + row * VS_ST + c4) =
                *(const float4*)(vg + (size_t)(j0 + row) * DHn + c4);
        }
        __syncthreads();

        // ---- S = (SCALE*Q).(K+E), 8x8 micro ----
        ull sa[8][4];
#pragma unroll
        for (int i = 0; i < 8; i++)
#pragma unroll
            for (int p = 0; p < 4; p++) sa[i][p] = 0ULL;

#pragma unroll 4
        for (int d = 0; d < 64; d++) {
            float4 q0 = *(const float4*)(Qs + d * QS_ST + ib);
            float4 q1 = *(const float4*)(Qs + d * QS_ST + ib + 4);
            ulonglong2 kA = *(const ulonglong2*)(Ks + d * KS_ST + jb);
            ulonglong2 kB = *(const ulonglong2*)(Ks + d * KS_ST + jb + 4);
            float4 e0 = *(const float4*)(Es + d * ES_ST + wb);
            float4 e1 = *(const float4*)(Es + d * ES_ST + wb + 4);
            float4 e2 = *(const float4*)(Es + d * ES_ST + wb + 8);
            float4 e3 = *(const float4*)(Es + d * ES_ST + wb + 12);
            float e[16] = { e0.x,e0.y,e0.z,e0.w, e1.x,e1.y,e1.z,e1.w,
                            e2.x,e2.y,e2.z,e2.w, e3.x,e3.y,e3.z,e3.w };
            ull pa[8] = { pk2(q0.x,q0.x), pk2(q0.y,q0.y), pk2(q0.z,q0.z), pk2(q0.w,q0.w),
                          pk2(q1.x,q1.x), pk2(q1.y,q1.y), pk2(q1.z,q1.z), pk2(q1.w,q1.w) };
            ull pb[4] = { kA.x, kA.y, kB.x, kB.y };
            ull pr[14];
#pragma unroll
            for (int o = 0; o < 14; o++) pr[o] = pk2(e[o], e[o+1]);
#pragma unroll
            for (int i = 0; i < 8; i++)
#pragma unroll
                for (int p = 0; p < 4; p++) {
                    ull t = add2(pb[p], pr[2*p + 7 - i]);
                    sa[i][p] = fma2(pa[i], t, sa[i][p]);
                }
        }

        __syncthreads();   // ALL warps done reading Ks/Es before Ps overwrite

        // ---- fused online softmax + P write (into Ks region) ----
#pragma unroll
        for (int i = 0; i < 8; i++) {
            float2 v0 = unpk(sa[i][0]);
            float2 v1 = unpk(sa[i][1]);
            float2 v2 = unpk(sa[i][2]);
            float2 v3 = unpk(sa[i][3]);
            float mx = fmaxf(fmaxf(fmaxf(v0.x, v0.y), fmaxf(v1.x, v1.y)),
                             fmaxf(fmaxf(v2.x, v2.y), fmaxf(v3.x, v3.y)));
#pragma unroll
            for (int o = 16; o; o >>= 1)
                mx = fmaxf(mx, __shfl_xor_sync(0xffffffffu, mx, o));
            const float mn = fmaxf(m_i[i], mx);
            const float al = __expf(m_i[i] - mn);
            m_i[i] = mn;
            float f0 = __expf(v0.x - mn), f1 = __expf(v0.y - mn);
            float f2 = __expf(v1.x - mn), f3 = __expf(v1.y - mn);
            float f4 = __expf(v2.x - mn), f5 = __expf(v2.y - mn);
            float f6 = __expf(v3.x - mn), f7 = __expf(v3.y - mn);
            float sum = ((f0 + f1) + (f2 + f3)) + ((f4 + f5) + (f6 + f7));
#pragma unroll
            for (int o = 16; o; o >>= 1)
                sum += __shfl_xor_sync(0xffffffffu, sum, o);
            l_i[i] = l_i[i] * al + sum;
            const ull aa = pk2(al, al);
#pragma unroll
            for (int p = 0; p < 4; p++)
                o_acc[i][p] = fma2(aa, o_acc[i][p], 0ULL);
            *(float4*)(Ps + (ib+i) * PS_ST + jb)     = make_float4(f0, f1, f2, f3);
            *(float4*)(Ps + (ib+i) * PS_ST + jb + 4) = make_float4(f4, f5, f6, f7);
        }
        __syncthreads();

        // ---- prefetch next tile's E window into Es (overlapped with AV) ----
        // Es region is dead from the post-S barrier until the next S phase.
        if (j0 + JT < Nn) {
            const int l0n = (j0 + JT) - i0 + 960;
#pragma unroll
            for (int u = 0; u < 20; u++) {
                const int r  = lane + (u % 10) * 32;
                const int c4 = grp * 4 + (u / 10) * 32;
                if (r < WIN) {
                    float4 v = *(const float4*)(Eg + (size_t)(l0n + r) * DHn + c4);
                    Es[(c4+0)*ES_ST + r] = v.x; Es[(c4+1)*ES_ST + r] = v.y;
                    Es[(c4+2)*ES_ST + r] = v.z; Es[(c4+3)*ES_ST + r] = v.w;
                }
            }
        }

        // ---- O += P @ V  (8i x 8d: cols c0..c0+3 and c0+32..c0+35, k-quarter tk) ----
#pragma unroll 2
        for (int k4 = 0; k4 < 64; k4 += 4) {
            const int kk = tk * 64 + k4;
            float4 pv[8];
#pragma unroll
            for (int i = 0; i < 8; i++)
                pv[i] = *(const float4*)(Ps + (ib+i) * PS_ST + kk);
#pragma unroll
            for (int u = 0; u < 4; u++) {
                float4 va = *(const float4*)(Vs + (kk+u) * VS_ST + c0);        // 16B lane stride: conflict-free
                float4 vb = *(const float4*)(Vs + (kk+u) * VS_ST + c0 + 32);
                const ull* wa = (const ull*)&va;
                const ull* wv = (const ull*)&vb;
#pragma unroll
                for (int i = 0; i < 8; i++) {
                    const float pf = (u == 0) ? pv[i].x : (u == 1) ? pv[i].y
                                   : (u == 2) ? pv[i].z : pv[i].w;
                    const ull pp = pk2(pf, pf);
                    o_acc[i][0] = fma2(pp, wa[0], o_acc[i][0]);
                    o_acc[i][1] = fma2(pp, wa[1], o_acc[i][1]);
                    o_acc[i][2] = fma2(pp, wv[0], o_acc[i][2]);
                    o_acc[i][3] = fma2(pp, wv[1], o_acc[i][3]);
                }
            }
        }
    }

    // ---- merge 4 k-quarters and epilogue (Om in Es region; E prefetch guarded off) ----
    __syncthreads();
#pragma unroll
    for (int i = 0; i < 8; i++)
#pragma unroll
        for (int p = 0; p < 4; p++) {
            float2 v = unpk(o_acc[i][p]);
            const int col = (p < 2) ? (c0 + 2*p) : (c0 + 32 + 2*(p-2));
            *(float2*)(Om + ((tk * 64 + ib + i) * 64 + col)) = v;
        }
    __syncthreads();

    if (tk == 0) {
        const int bb = bh >> 3, hh = bh & 7;
#pragma unroll
        for (int i = 0; i < 8; i++) {
            const int gi = i0 + ib + i;
            const float f = phase[(size_t)bh * Nn + gi] / l_i[i];
#pragma unroll
            for (int half = 0; half < 2; half++) {
                const int c = c0 + half * 32;
                float4 a0 = *(const float4*)(Om + ((ib + i) * 64 + c));
                float4 a1 = *(const float4*)(Om + ((64 + ib + i) * 64 + c));
                float4 a2 = *(const float4*)(Om + ((128 + ib + i) * 64 + c));
                float4 a3 = *(const float4*)(Om + ((192 + ib + i) * 64 + c));
                float4 o;
                o.x = ((a0.x + a1.x) + (a2.x + a3.x)) * f;
                o.y = ((a0.y + a1.y) + (a2.y + a3.y)) * f;
                o.z = ((a0.z + a1.z) + (a2.z + a3.z)) * f;
                o.w = ((a0.w + a1.w) + (a2.w + a3.w)) * f;
                *(float4*)&g_otmp[(size_t)(bb * Nn + gi) * Dn + hh * 64 + c] = o;
            }
        }
    }
}

// ---------------------------------------------------------------------------
extern "C" void kernel_launch(void* const* d_in, const int* in_sizes, int n_in,
                              void* d_out, int out_size)
{
    const float* x     = (const float*)d_in[0];
    const float* phase = (const float*)d_in[1];
    const float* E     = (const float*)d_in[2];
    const float* Wq    = (const float*)d_in[3];
    const float* Wk    = (const float*)d_in[4];
    const float* Wv    = (const float*)d_in[5];
    const float* Wo    = (const float*)d_in[6];
    const float* bo    = (const float*)d_in[7];
    float* out = (float*)d_out;

    static const bool s_init = []() {
        cudaFuncSetAttribute(flash_attn, cudaFuncAttributeMaxDynamicSharedMemorySize,
                             SMEM_BYTES);
        return true;
    }();
    (void)s_init;

    dim3 gproj(Dn / 128, (Bn * Nn) / 128);   // (4, 64)

    gemm128<0><<<gproj, 256>>>(x, Wq, nullptr, nullptr);
    gemm128<1><<<gproj, 256>>>(x, Wk, nullptr, nullptr);
    gemm128<2><<<gproj, 256>>>(x, Wv, nullptr, nullptr);

    flash_attn<<<dim3(Nn / 64, BHn), 256, SMEM_BYTES>>>(E, phase);

    gemm128<3><<<gproj, 256>>>(nullptr, Wo, bo, out);
}